// round 9
// baseline (speedup 1.0000x reference)
#include <cuda_runtime.h>
#include <cstdint>

// Problem constants
#define D_MODEL   1024
#define NUM_HEADS 16
#define DEPTH     64
#define BATCH     4
#define SEQ       2048
#define ROWS_TOT  (BATCH * SEQ)   // 8192
#define ATT_SCALE 0.125f          // 1/sqrt(DEPTH) = 2^-3 (tf32-exact scaling)

// ---------------------------------------------------------------------------
// Scratch (device globals -- no allocation allowed)
// ---------------------------------------------------------------------------
__device__ float g_qp[ROWS_TOT * D_MODEL];
__device__ float g_kp[ROWS_TOT * D_MODEL];
__device__ float g_vp[ROWS_TOT * D_MODEL];
__device__ float g_op[ROWS_TOT * D_MODEL];
__device__ float g_xc[ROWS_TOT * D_MODEL];   // tf32-rounded activations
__device__ float g_wc[D_MODEL * D_MODEL];    // tf32-rounded weights

// ---------------------------------------------------------------------------
// Common helpers
// ---------------------------------------------------------------------------
__device__ __forceinline__ uint32_t smem_u32(const void* p) {
    uint32_t a;
    asm("{ .reg .u64 t; cvta.to.shared.u64 t, %1; cvt.u32.u64 %0, t; }"
        : "=r"(a) : "l"(p));
    return a;
}
__device__ __forceinline__ float rna_tf32f(float x) {
    uint32_t u;
    asm("cvt.rna.tf32.f32 %0, %1;" : "=r"(u) : "f"(x));
    return __uint_as_float(u);
}
__device__ __forceinline__ uint32_t rna_tf32u(float x) {
    uint32_t u;
    asm("cvt.rna.tf32.f32 %0, %1;" : "=r"(u) : "f"(x));
    return u;
}

#define CP_ASYNC16(dst, src) \
    asm volatile("cp.async.cg.shared.global [%0], [%1], 16;" :: "r"(dst), "l"(src) : "memory")
#define CP_COMMIT()  asm volatile("cp.async.commit_group;" ::: "memory")
#define CP_WAIT0()   asm volatile("cp.async.wait_group 0;" ::: "memory")
#define CP_WAIT2()   asm volatile("cp.async.wait_group 2;" ::: "memory")

// mma.sync m16n8k8 tf32 (documented fragment layouts; proven in attention)
__device__ __forceinline__ void mma_tf32(float c[4], uint32_t a0, uint32_t a1,
                                         uint32_t a2, uint32_t a3,
                                         uint32_t b0, uint32_t b1) {
    asm volatile(
        "mma.sync.aligned.m16n8k8.row.col.f32.tf32.tf32.f32 "
        "{%0,%1,%2,%3}, {%4,%5,%6,%7}, {%8,%9}, {%0,%1,%2,%3};"
        : "+f"(c[0]), "+f"(c[1]), "+f"(c[2]), "+f"(c[3])
        : "r"(a0), "r"(a1), "r"(a2), "r"(a3), "r"(b0), "r"(b1));
}

// ---------------------------------------------------------------------------
// tf32-rna rounding pass
// ---------------------------------------------------------------------------
__global__ void rna_tf32_kernel(const float4* __restrict__ x, float4* __restrict__ y) {
    const int i = blockIdx.x * blockDim.x + threadIdx.x;
    float4 v = x[i];
    float4 o;
    o.x = rna_tf32f(v.x); o.y = rna_tf32f(v.y);
    o.z = rna_tf32f(v.z); o.w = rna_tf32f(v.w);
    y[i] = o;
}

// ---------------------------------------------------------------------------
// mma.sync tf32 GEMM: Y[m,n] = sum_k X[m,k] * W[n,k] + bias[n]  (x @ W.T + b)
// CTA tile 128x256, warp tile 64x64 (2x4 warp grid), K-tile 32, 3 stages.
// Smem rows padded to LD=36 floats (36 mod 32 = 4 -> frag lanes hit banks
// 4g+t, all distinct -> conflict-free LDS.32 fragment loads).
// ---------------------------------------------------------------------------
#define GM 128
#define GN 256
#define GK 32
#define GLD 36
#define A_FLT (GM * GLD)                 // 4608
#define B_FLT (GN * GLD)                 // 9216
#define STG_FLT (A_FLT + B_FLT)          // 13824
#define GSTG 3
#define GEMM_SMEM (GSTG * STG_FLT * 4)   // 165888 bytes
#define NKT (D_MODEL / GK)               // 32

__global__ __launch_bounds__(256) void gemm_mma_tf32_kernel(
    const float* __restrict__ X, const float* __restrict__ W,
    const float* __restrict__ bias, float* __restrict__ Y, int round_out)
{
    extern __shared__ float sm[];
    const int tid  = threadIdx.x;
    const int wid  = tid >> 5;
    const int lane = tid & 31;
    const int g = lane >> 2;
    const int t = lane & 3;
    const int warpM = wid >> 2;          // 0..1
    const int warpN = wid & 3;           // 0..3
    const int n0 = blockIdx.x * GN;
    const int m0 = blockIdx.y * GM;

    auto load_stage = [&](int kt, int buf) {
        const uint32_t AsU = smem_u32(sm) + (uint32_t)(buf * STG_FLT) * 4;
        const uint32_t BsU = AsU + A_FLT * 4;
        const float* Xg = X + (size_t)m0 * D_MODEL + kt * GK;
        const float* Wg = W + (size_t)n0 * D_MODEL + kt * GK;
#pragma unroll
        for (int j = 0; j < 4; j++) {          // A: 128 rows x 8 chunks
            const int id = tid + (j << 8);
            const int row = id >> 3, cc = id & 7;
            CP_ASYNC16(AsU + (uint32_t)((row * GLD + cc * 4) * 4),
                       Xg + (size_t)row * D_MODEL + cc * 4);
        }
#pragma unroll
        for (int j = 0; j < 8; j++) {          // B: 256 rows x 8 chunks
            const int id = tid + (j << 8);
            const int row = id >> 3, cc = id & 7;
            CP_ASYNC16(BsU + (uint32_t)((row * GLD + cc * 4) * 4),
                       Wg + (size_t)row * D_MODEL + cc * 4);
        }
    };

    float acc[4][8][4];
#pragma unroll
    for (int mi = 0; mi < 4; mi++)
#pragma unroll
        for (int nj = 0; nj < 8; nj++) {
            acc[mi][nj][0] = 0.0f; acc[mi][nj][1] = 0.0f;
            acc[mi][nj][2] = 0.0f; acc[mi][nj][3] = 0.0f;
        }

#pragma unroll 1
    for (int s = 0; s < GSTG; s++) { load_stage(s, s); CP_COMMIT(); }

#pragma unroll 1
    for (int kt = 0; kt < NKT; kt++) {
        CP_WAIT2();
        __syncthreads();

        const float* As = sm + (kt % GSTG) * STG_FLT;
        const float* Bs = As + A_FLT;
        const float* Abase = As + (warpM * 64 + g) * GLD + t;
        const float* Bbase = Bs + (warpN * 64 + g) * GLD + t;

#pragma unroll
        for (int kc = 0; kc < 4; kc++) {
            uint32_t a[4][4], b[8][2];
#pragma unroll
            for (int mi = 0; mi < 4; mi++) {
                const float* ap = Abase + mi * (16 * GLD) + kc * 8;
                a[mi][0] = __float_as_uint(ap[0]);
                a[mi][1] = __float_as_uint(ap[8 * GLD]);
                a[mi][2] = __float_as_uint(ap[4]);
                a[mi][3] = __float_as_uint(ap[8 * GLD + 4]);
            }
#pragma unroll
            for (int nj = 0; nj < 8; nj++) {
                const float* bp = Bbase + nj * (8 * GLD) + kc * 8;
                b[nj][0] = __float_as_uint(bp[0]);
                b[nj][1] = __float_as_uint(bp[4]);
            }
#pragma unroll
            for (int mi = 0; mi < 4; mi++)
#pragma unroll
                for (int nj = 0; nj < 8; nj++)
                    mma_tf32(acc[mi][nj], a[mi][0], a[mi][1], a[mi][2], a[mi][3],
                             b[nj][0], b[nj][1]);
        }
        __syncthreads();

        const int nk = kt + GSTG;
        if (nk < NKT) load_stage(nk, nk % GSTG);
        CP_COMMIT();
    }

    // Epilogue: direct float2 stores from C fragments (+bias, optional rna)
    float2 bv[8];
#pragma unroll
    for (int nj = 0; nj < 8; nj++)
        bv[nj] = *(const float2*)&bias[n0 + warpN * 64 + nj * 8 + 2 * t];

#pragma unroll
    for (int mi = 0; mi < 4; mi++) {
        const int r0 = m0 + warpM * 64 + mi * 16 + g;
        float* y0 = Y + (size_t)r0 * D_MODEL + n0 + warpN * 64 + 2 * t;
        float* y1 = y0 + (size_t)8 * D_MODEL;
#pragma unroll
        for (int nj = 0; nj < 8; nj++) {
            float2 v0 = make_float2(acc[mi][nj][0] + bv[nj].x, acc[mi][nj][1] + bv[nj].y);
            float2 v1 = make_float2(acc[mi][nj][2] + bv[nj].x, acc[mi][nj][3] + bv[nj].y);
            if (round_out) {
                v0.x = rna_tf32f(v0.x); v0.y = rna_tf32f(v0.y);
                v1.x = rna_tf32f(v1.x); v1.y = rna_tf32f(v1.y);
            }
            *(float2*)(y0 + nj * 8) = v0;
            *(float2*)(y1 + nj * 8) = v1;
        }
    }
}

// ---------------------------------------------------------------------------
// Tensor-core flash attention (mma.sync m16n8k8 tf32) -- passing in R5.
// Epilogue emits rna-tf32-rounded O (dense GEMM skips its rna pass).
// ---------------------------------------------------------------------------
#define LDQ 68
#define LDK 68
#define LDV 72
#define LDP 68
#define OFF_KS  (128 * LDQ)
#define OFF_VR  (OFF_KS + 64 * LDK)
#define OFF_PS  (OFF_VR + 64 * LDV)
#define ATTN_SMEM ((OFF_PS + 128 * LDP) * 4)

__global__ __launch_bounds__(256, 2) void attn_mma_kernel(
    const float* __restrict__ Q, const float* __restrict__ K,
    const float* __restrict__ V, float* __restrict__ O)
{
    extern __shared__ float smA[];
    float* Qs = smA;
    const uint32_t QsU = smem_u32(Qs);
    const uint32_t KsU = QsU + OFF_KS * 4;
    const uint32_t VrU = QsU + OFF_VR * 4;
    const uint32_t PsU = QsU + OFF_PS * 4;

    const int tid  = threadIdx.x;
    const int wid  = tid >> 5;
    const int lane = tid & 31;
    const int g = lane >> 2;
    const int t = lane & 3;
    const int q0 = blockIdx.x * 128;
    const int h  = blockIdx.y;
    const int b  = blockIdx.z;
    const size_t base = (size_t)b * SEQ * D_MODEL + (size_t)h * DEPTH;

    const int row0 = wid * 16 + g;
    const int row1 = row0 + 8;

#pragma unroll
    for (int j = 0; j < 8; j++) {
        const int id = tid + (j << 8);
        const int r  = id >> 4;
        const int c4 = (id & 15) << 2;
        float4 v = *(const float4*)&Q[base + (size_t)(q0 + r) * D_MODEL + c4];
        v.x *= ATT_SCALE; v.y *= ATT_SCALE; v.z *= ATT_SCALE; v.w *= ATT_SCALE;
        *(float4*)&Qs[r * LDQ + c4] = v;
    }

    float m0 = -3.0e38f, m1 = -3.0e38f, l0 = 0.0f, l1 = 0.0f;
    float o[8][4];
#pragma unroll
    for (int j = 0; j < 8; j++) { o[j][0] = o[j][1] = o[j][2] = o[j][3] = 0.0f; }

    const float* Kg = K + base;
    const float* Vg = V + base;

#pragma unroll 1
    for (int kt = 0; kt < SEQ / 64; kt++) {
        __syncthreads();

        const int kv0 = kt * 64;
#pragma unroll
        for (int j = 0; j < 4; j++) {
            const int id  = tid + (j << 8);
            const int r   = id >> 4;
            const int c16 = id & 15;
            CP_ASYNC16(KsU + (uint32_t)(r * LDK * 4 + c16 * 16),
                       Kg + (size_t)(kv0 + r) * D_MODEL + c16 * 4);
            CP_ASYNC16(VrU + (uint32_t)(r * LDV * 4 + c16 * 16),
                       Vg + (size_t)(kv0 + r) * D_MODEL + c16 * 4);
        }
        CP_COMMIT();
        CP_WAIT0();
        __syncthreads();

        float s[8][4];
#pragma unroll
        for (int j = 0; j < 8; j++) { s[j][0] = s[j][1] = s[j][2] = s[j][3] = 0.0f; }

#pragma unroll
        for (int kc = 0; kc < 8; kc++) {
            uint32_t a0, a1, a2, a3;
            asm volatile("ld.shared.b32 %0, [%1];" : "=r"(a0) : "r"(QsU + (row0 * LDQ + kc * 8 + t) * 4));
            asm volatile("ld.shared.b32 %0, [%1];" : "=r"(a1) : "r"(QsU + (row1 * LDQ + kc * 8 + t) * 4));
            asm volatile("ld.shared.b32 %0, [%1];" : "=r"(a2) : "r"(QsU + (row0 * LDQ + kc * 8 + t + 4) * 4));
            asm volatile("ld.shared.b32 %0, [%1];" : "=r"(a3) : "r"(QsU + (row1 * LDQ + kc * 8 + t + 4) * 4));
#pragma unroll
            for (int j = 0; j < 8; j++) {
                uint32_t b0, b1;
                asm volatile("ld.shared.b32 %0, [%1];" : "=r"(b0) : "r"(KsU + ((8 * j + g) * LDK + kc * 8 + t) * 4));
                asm volatile("ld.shared.b32 %0, [%1];" : "=r"(b1) : "r"(KsU + ((8 * j + g) * LDK + kc * 8 + t + 4) * 4));
                mma_tf32(s[j], a0, a1, a2, a3, b0, b1);
            }
        }

        float tm0 = fmaxf(s[0][0], s[0][1]);
        float tm1 = fmaxf(s[0][2], s[0][3]);
#pragma unroll
        for (int j = 1; j < 8; j++) {
            tm0 = fmaxf(tm0, fmaxf(s[j][0], s[j][1]));
            tm1 = fmaxf(tm1, fmaxf(s[j][2], s[j][3]));
        }
        tm0 = fmaxf(tm0, __shfl_xor_sync(0xffffffffu, tm0, 1));
        tm0 = fmaxf(tm0, __shfl_xor_sync(0xffffffffu, tm0, 2));
        tm1 = fmaxf(tm1, __shfl_xor_sync(0xffffffffu, tm1, 1));
        tm1 = fmaxf(tm1, __shfl_xor_sync(0xffffffffu, tm1, 2));

        const float mn0 = fmaxf(m0, tm0);
        const float mn1 = fmaxf(m1, tm1);
        const float corr0 = __expf(m0 - mn0);
        const float corr1 = __expf(m1 - mn1);
        m0 = mn0; m1 = mn1;

        float sum0 = 0.0f, sum1 = 0.0f;
#pragma unroll
        for (int j = 0; j < 8; j++) {
            const float p00 = __expf(s[j][0] - mn0);
            const float p01 = __expf(s[j][1] - mn0);
            const float p10 = __expf(s[j][2] - mn1);
            const float p11 = __expf(s[j][3] - mn1);
            sum0 += p00 + p01;
            sum1 += p10 + p11;
            uint2 w0 = make_uint2(rna_tf32u(p00), rna_tf32u(p01));
            uint2 w1 = make_uint2(rna_tf32u(p10), rna_tf32u(p11));
            asm volatile("st.shared.v2.b32 [%0], {%1, %2};" ::
                         "r"(PsU + (row0 * LDP + 8 * j + 2 * t) * 4), "r"(w0.x), "r"(w0.y) : "memory");
            asm volatile("st.shared.v2.b32 [%0], {%1, %2};" ::
                         "r"(PsU + (row1 * LDP + 8 * j + 2 * t) * 4), "r"(w1.x), "r"(w1.y) : "memory");
        }
        sum0 += __shfl_xor_sync(0xffffffffu, sum0, 1);
        sum0 += __shfl_xor_sync(0xffffffffu, sum0, 2);
        sum1 += __shfl_xor_sync(0xffffffffu, sum1, 1);
        sum1 += __shfl_xor_sync(0xffffffffu, sum1, 2);
        l0 = l0 * corr0 + sum0;
        l1 = l1 * corr1 + sum1;
#pragma unroll
        for (int j = 0; j < 8; j++) {
            o[j][0] *= corr0; o[j][1] *= corr0;
            o[j][2] *= corr1; o[j][3] *= corr1;
        }
        __syncwarp();

#pragma unroll
        for (int kc = 0; kc < 8; kc++) {
            uint32_t a0, a1, a2, a3;
            asm volatile("ld.shared.b32 %0, [%1];" : "=r"(a0) : "r"(PsU + (row0 * LDP + kc * 8 + t) * 4));
            asm volatile("ld.shared.b32 %0, [%1];" : "=r"(a1) : "r"(PsU + (row1 * LDP + kc * 8 + t) * 4));
            asm volatile("ld.shared.b32 %0, [%1];" : "=r"(a2) : "r"(PsU + (row0 * LDP + kc * 8 + t + 4) * 4));
            asm volatile("ld.shared.b32 %0, [%1];" : "=r"(a3) : "r"(PsU + (row1 * LDP + kc * 8 + t + 4) * 4));
#pragma unroll
            for (int j = 0; j < 8; j++) {
                uint32_t b0, b1;
                asm volatile("ld.shared.b32 %0, [%1];" : "=r"(b0) : "r"(VrU + ((kc * 8 + t) * LDV + 8 * j + g) * 4));
                asm volatile("ld.shared.b32 %0, [%1];" : "=r"(b1) : "r"(VrU + ((kc * 8 + t + 4) * LDV + 8 * j + g) * 4));
                mma_tf32(o[j], a0, a1, a2, a3, b0, b1);
            }
        }
    }

    const float inv0 = 1.0f / l0;
    const float inv1 = 1.0f / l1;
    float* or0 = O + base + (size_t)(q0 + row0) * D_MODEL;
    float* or1 = O + base + (size_t)(q0 + row1) * D_MODEL;
#pragma unroll
    for (int j = 0; j < 8; j++) {
        *(float2*)(or0 + 8 * j + 2 * t) =
            make_float2(rna_tf32f(o[j][0] * inv0), rna_tf32f(o[j][1] * inv0));
        *(float2*)(or1 + 8 * j + 2 * t) =
            make_float2(rna_tf32f(o[j][2] * inv1), rna_tf32f(o[j][3] * inv1));
    }
}

// ---------------------------------------------------------------------------
// Launch
// ---------------------------------------------------------------------------
extern "C" void kernel_launch(void* const* d_in, const int* in_sizes, int n_in,
                              void* d_out, int out_size)
{
    (void)in_sizes; (void)n_in; (void)out_size;
    const float* v_in = (const float*)d_in[0];
    const float* k_in = (const float*)d_in[1];
    const float* q_in = (const float*)d_in[2];
    const float* wq   = (const float*)d_in[3];
    const float* bq   = (const float*)d_in[4];
    const float* wk   = (const float*)d_in[5];
    const float* bk   = (const float*)d_in[6];
    const float* wv   = (const float*)d_in[7];
    const float* bv   = (const float*)d_in[8];
    const float* wd   = (const float*)d_in[9];
    const float* bd   = (const float*)d_in[10];

    float *pq, *pk, *pv, *po, *xc, *wc;
    cudaGetSymbolAddress((void**)&pq, g_qp);
    cudaGetSymbolAddress((void**)&pk, g_kp);
    cudaGetSymbolAddress((void**)&pv, g_vp);
    cudaGetSymbolAddress((void**)&po, g_op);
    cudaGetSymbolAddress((void**)&xc, g_xc);
    cudaGetSymbolAddress((void**)&wc, g_wc);

    cudaFuncSetAttribute(gemm_mma_tf32_kernel,
                         cudaFuncAttributeMaxDynamicSharedMemorySize, GEMM_SMEM);
    cudaFuncSetAttribute(attn_mma_kernel,
                         cudaFuncAttributeMaxDynamicSharedMemorySize, ATTN_SMEM);

    const int xBlk = (ROWS_TOT * D_MODEL / 4) / 256;   // 8192
    const int wBlk = (D_MODEL * D_MODEL / 4) / 256;    // 1024
    dim3 ggrid(D_MODEL / GN, ROWS_TOT / GM);           // (4, 64)

    // Q projection (rna-tf32 output for attention)
    rna_tf32_kernel<<<xBlk, 256>>>((const float4*)q_in, (float4*)xc);
    rna_tf32_kernel<<<wBlk, 256>>>((const float4*)wq, (float4*)wc);
    gemm_mma_tf32_kernel<<<ggrid, 256, GEMM_SMEM>>>(xc, wc, bq, pq, 1);
    // K projection
    rna_tf32_kernel<<<xBlk, 256>>>((const float4*)k_in, (float4*)xc);
    rna_tf32_kernel<<<wBlk, 256>>>((const float4*)wk, (float4*)wc);
    gemm_mma_tf32_kernel<<<ggrid, 256, GEMM_SMEM>>>(xc, wc, bk, pk, 1);
    // V projection
    rna_tf32_kernel<<<xBlk, 256>>>((const float4*)v_in, (float4*)xc);
    rna_tf32_kernel<<<wBlk, 256>>>((const float4*)wv, (float4*)wc);
    gemm_mma_tf32_kernel<<<ggrid, 256, GEMM_SMEM>>>(xc, wc, bv, pv, 1);

    // Tensor-core attention (emits rna-rounded O)
    attn_mma_kernel<<<dim3(SEQ / 128, NUM_HEADS, BATCH), 256, ATTN_SMEM>>>(pq, pk, pv, po);

    // Dense projection (po already tf32-rounded; no extra rna pass)
    rna_tf32_kernel<<<wBlk, 256>>>((const float4*)wd, (float4*)wc);
    gemm_mma_tf32_kernel<<<ggrid, 256, GEMM_SMEM>>>(po, wc, bd, (float*)d_out, 0);
}